// round 2
// baseline (speedup 1.0000x reference)
#include <cuda_runtime.h>

// BiLIF: out[t] = (s1[t] + s2[t]) / 2
//   s1 = LIF(x,       tau=1/0.75, v_th=0.75)   forward in t
//   s2 = LIF(flip(x), tau=1/0.75, v_th=1.25)   over reversed input, NOT flipped back
// LIF step: h = v + (x - v)*0.75 = 0.25*v + 0.75*x ; s = (h >= v_th) ; v = s ? 0 : h
//
// x [16, 64, 65536] fp32 -> out same shape. Per-neuron scan over T=16:
// cache the whole series in registers (16 x float4 per thread), do both scans
// register-resident. HBM traffic = 1 read + 1 write per element (512 MB total).

constexpr int T = 16;

__global__ __launch_bounds__(256)
void bilif_kernel(const float4* __restrict__ x4,
                  float4* __restrict__ out4,
                  int s4)   // float4 elements per time step (B*N/4)
{
    const int i = blockIdx.x * blockDim.x + threadIdx.x;
    if (i >= s4) return;

    // ---- load full time series for 4 neurons (16 batched LDG.128, MLP=16) ----
    // Streaming loads: no reuse, evict-first to keep L2 clean.
    float4 xv[T];
#pragma unroll
    for (int t = 0; t < T; ++t)
        xv[t] = __ldcs(&x4[t * s4 + i]);

    // ---- forward scan: s1 spikes -> per-lane bitmasks, v_th = 0.75 ----
    float v0 = 0.f, v1 = 0.f, v2 = 0.f, v3 = 0.f;
    unsigned m0 = 0u, m1 = 0u, m2 = 0u, m3 = 0u;
#pragma unroll
    for (int t = 0; t < T; ++t) {
        float h0 = fmaf(0.25f, v0, 0.75f * xv[t].x);
        float h1 = fmaf(0.25f, v1, 0.75f * xv[t].y);
        float h2 = fmaf(0.25f, v2, 0.75f * xv[t].z);
        float h3 = fmaf(0.25f, v3, 0.75f * xv[t].w);
        bool s0 = (h0 >= 0.75f);
        bool s1 = (h1 >= 0.75f);
        bool s2 = (h2 >= 0.75f);
        bool s3 = (h3 >= 0.75f);
        m0 |= (unsigned)s0 << t;
        m1 |= (unsigned)s1 << t;
        m2 |= (unsigned)s2 << t;
        m3 |= (unsigned)s3 << t;
        v0 = s0 ? 0.f : h0;
        v1 = s1 ? 0.f : h1;
        v2 = s2 ? 0.f : h2;
        v3 = s3 ? 0.f : h3;
    }

    // ---- backward scan on reversed input, v_th = 1.25; fuse output write ----
    v0 = v1 = v2 = v3 = 0.f;
#pragma unroll
    for (int k = 0; k < T; ++k) {
        const float4 xi = xv[T - 1 - k];   // rev[k] = x[T-1-k]
        float h0 = fmaf(0.25f, v0, 0.75f * xi.x);
        float h1 = fmaf(0.25f, v1, 0.75f * xi.y);
        float h2 = fmaf(0.25f, v2, 0.75f * xi.z);
        float h3 = fmaf(0.25f, v3, 0.75f * xi.w);
        bool s0 = (h0 >= 1.25f);
        bool s1 = (h1 >= 1.25f);
        bool s2 = (h2 >= 1.25f);
        bool s3 = (h3 >= 1.25f);
        v0 = s0 ? 0.f : h0;
        v1 = s1 ? 0.f : h1;
        v2 = s2 ? 0.f : h2;
        v3 = s3 ? 0.f : h3;
        float4 o;
        o.x = 0.5f * ((float)((m0 >> k) & 1u) + (float)s0);
        o.y = 0.5f * ((float)((m1 >> k) & 1u) + (float)s1);
        o.z = 0.5f * ((float)((m2 >> k) & 1u) + (float)s2);
        o.w = 0.5f * ((float)((m3 >> k) & 1u) + (float)s3);
        __stcs(&out4[k * s4 + i], o);      // streaming store: never re-read
    }
}

extern "C" void kernel_launch(void* const* d_in, const int* in_sizes, int n_in,
                              void* d_out, int out_size)
{
    const float* x = (const float*)d_in[0];
    float* out = (float*)d_out;

    const int total = in_sizes[0];          // T * B * N = 67,108,864
    const int per_t = total / T;            // B * N = 4,194,304
    const int s4 = per_t / 4;               // 1,048,576 float4 per time step

    const int threads = 256;
    const int blocks = (s4 + threads - 1) / threads;   // 4096
    bilif_kernel<<<blocks, threads>>>((const float4*)x, (float4*)out, s4);
}

// round 3
// speedup vs baseline: 1.0271x; 1.0271x over previous
#include <cuda_runtime.h>

// BiLIF: out[t] = (s1[t] + s2[t]) / 2
//   s1 = LIF(x,       tau=1/0.75, v_th=0.75)   forward in t
//   s2 = LIF(flip(x), tau=1/0.75, v_th=1.25)   over reversed input, NOT flipped back
// LIF step: h = 0.25*v + 0.75*x ; s = (h >= v_th) ; v = s ? 0 : h
//
// x [16, 64, 65536] fp32 -> out same. R2 postmortem: float4/thread -> 118 regs,
// occ 21.7%, DRAM 70%. This version: float2/thread (2 neurons), halving the
// register-resident series to 32 regs -> target 3-4 blocks/SM, smoother DRAM.

constexpr int T = 16;

__global__ __launch_bounds__(256)
void bilif_kernel(const float2* __restrict__ x2,
                  float2* __restrict__ out2,
                  int s2)   // float2 elements per time step (B*N/2)
{
    const int i = blockIdx.x * blockDim.x + threadIdx.x;
    if (i >= s2) return;

    // ---- load full time series for 2 neurons (16 LDG.64, streaming) ----
    float2 xv[T];
#pragma unroll
    for (int t = 0; t < T; ++t)
        xv[t] = __ldcs(&x2[t * s2 + i]);

    // ---- forward scan: s1 spikes -> per-lane bitmasks, v_th = 0.75 ----
    float v0 = 0.f, v1 = 0.f;
    unsigned m0 = 0u, m1 = 0u;
#pragma unroll
    for (int t = 0; t < T; ++t) {
        float h0 = fmaf(0.25f, v0, 0.75f * xv[t].x);
        float h1 = fmaf(0.25f, v1, 0.75f * xv[t].y);
        bool s0 = (h0 >= 0.75f);
        bool s1 = (h1 >= 0.75f);
        m0 |= (unsigned)s0 << t;
        m1 |= (unsigned)s1 << t;
        v0 = s0 ? 0.f : h0;
        v1 = s1 ? 0.f : h1;
    }

    // ---- backward scan on reversed input, v_th = 1.25; fused output write ----
    v0 = 0.f; v1 = 0.f;
#pragma unroll
    for (int k = 0; k < T; ++k) {
        const float2 xi = xv[T - 1 - k];   // rev[k] = x[T-1-k]
        float h0 = fmaf(0.25f, v0, 0.75f * xi.x);
        float h1 = fmaf(0.25f, v1, 0.75f * xi.y);
        bool s0 = (h0 >= 1.25f);
        bool s1 = (h1 >= 1.25f);
        v0 = s0 ? 0.f : h0;
        v1 = s1 ? 0.f : h1;
        float2 o;
        o.x = 0.5f * ((float)((m0 >> k) & 1u) + (float)s0);
        o.y = 0.5f * ((float)((m1 >> k) & 1u) + (float)s1);
        __stcs(&out2[k * s2 + i], o);      // streaming store: never re-read
    }
}

extern "C" void kernel_launch(void* const* d_in, const int* in_sizes, int n_in,
                              void* d_out, int out_size)
{
    const float* x = (const float*)d_in[0];
    float* out = (float*)d_out;

    const int total = in_sizes[0];          // T * B * N = 67,108,864
    const int per_t = total / T;            // B * N = 4,194,304
    const int s2 = per_t / 2;               // 2,097,152 float2 per time step

    const int threads = 256;
    const int blocks = (s2 + threads - 1) / threads;   // 8192
    bilif_kernel<<<blocks, threads>>>((const float2*)x, (float2*)out, s2);
}